// round 2
// baseline (speedup 1.0000x reference)
#include <cuda_runtime.h>
#include <math.h>
#include <stdint.h>

#define NN 50000
#define NE 1600000
#define EPSV 1e-5f

// ---------------- scratch (device globals; no allocation allowed) ----------
__device__ float g_h[2][(size_t)NN * 256];      // ping-pong hidden states
__device__ float g_hw[(size_t)NN * 256];        // h @ W
__device__ int   g_counts[NN];
__device__ int   g_rowptr[NN + 1];
__device__ int   g_fill[NN];
__device__ int   g_srcs[NE];
__device__ float g_coef[NE];
__device__ float g_dis[NN];

// ---------------- CSR build ------------------------------------------------
__global__ void zero_counts_k() {
    int i = blockIdx.x * blockDim.x + threadIdx.x;
    if (i < NN) g_counts[i] = 0;
}

__global__ void hist_k(const int* __restrict__ ei) {
    int e = blockIdx.x * blockDim.x + threadIdx.x;
    if (e < NE) atomicAdd(&g_counts[ei[NE + e]], 1);
}

// single block, 1024 threads: exclusive scan of counts -> rowptr, fill; dis
__global__ void scan_k() {
    __shared__ int sh[1024];
    int t = threadIdx.x;
    const int per = (NN + 1023) / 1024;
    int beg = t * per;
    int end = beg + per; if (end > NN) end = NN;
    if (beg > NN) beg = NN;
    int s = 0;
    for (int i = beg; i < end; i++) s += g_counts[i];
    sh[t] = s;
    __syncthreads();
    if (t == 0) {
        int acc = 0;
        for (int i = 0; i < 1024; i++) { int v = sh[i]; sh[i] = acc; acc += v; }
    }
    __syncthreads();
    int off = sh[t];
    for (int i = beg; i < end; i++) {
        g_rowptr[i] = off;
        g_fill[i]   = off;
        int c = g_counts[i];
        off += c;
        g_dis[i] = rsqrtf((float)c + 1.0f);
    }
    if (end == NN) g_rowptr[NN] = off;  // all tail threads write the same total
}

__global__ void scatter_k(const int* __restrict__ ei) {
    int e = blockIdx.x * blockDim.x + threadIdx.x;
    if (e < NE) {
        int s = ei[e];
        int d = ei[NE + e];
        int pos = atomicAdd(&g_fill[d], 1);
        g_srcs[pos] = s;
        g_coef[pos] = g_dis[s] * g_dis[d];
    }
}

// ---------------- GEMM: C[M,256] = A[M,K] * B[K,256] -----------------------
// BM=128, BN=64, BK=16, 256 threads, 8x4 per thread.
// As stored k-major-transposed: As[k][row] so inner loop reads are LDS.128.
__global__ __launch_bounds__(256) void gemm_k(
        const float* __restrict__ A, const float* __restrict__ B,
        float* __restrict__ C, int M, int K) {
    const int N = 256;
    __shared__ float As[16][132];   // +4 pad
    __shared__ float Bs[16][68];    // +4 pad

    int t  = threadIdx.x;           // 0..255
    int bm = blockIdx.y * 128;
    int bn = blockIdx.x * 64;
    int tx = t & 15;                // col group: cols tx*4 .. tx*4+3
    int ty = t >> 4;                // row group: rows ty*8 .. ty*8+7

    int arow  = t >> 2;             // 0..63 (loads rows arow, arow+64)
    int acol4 = (t & 3) * 4;        // 0,4,8,12
    int brow  = t >> 4;             // 0..15
    int bcol4 = (t & 15) * 4;       // 0..60

    float acc[8][4];
#pragma unroll
    for (int i = 0; i < 8; i++)
#pragma unroll
        for (int j = 0; j < 4; j++) acc[i][j] = 0.f;

    for (int k0 = 0; k0 < K; k0 += 16) {
#pragma unroll
        for (int h = 0; h < 2; h++) {
            int r = bm + arow + h * 64;
            float4 av = make_float4(0.f, 0.f, 0.f, 0.f);
            if (r < M)
                av = *(const float4*)(A + (size_t)r * K + k0 + acol4);
            int sr = arow + h * 64;
            As[acol4 + 0][sr] = av.x;
            As[acol4 + 1][sr] = av.y;
            As[acol4 + 2][sr] = av.z;
            As[acol4 + 3][sr] = av.w;
        }
        float4 bv = *(const float4*)(B + (size_t)(k0 + brow) * N + bn + bcol4);
        *(float4*)&Bs[brow][bcol4] = bv;
        __syncthreads();

#pragma unroll
        for (int k = 0; k < 16; k++) {
            float4 a0 = *(const float4*)&As[k][ty * 8];
            float4 a1 = *(const float4*)&As[k][ty * 8 + 4];
            float4 b4 = *(const float4*)&Bs[k][tx * 4];
            float ar[8] = {a0.x, a0.y, a0.z, a0.w, a1.x, a1.y, a1.z, a1.w};
            float br[4] = {b4.x, b4.y, b4.z, b4.w};
#pragma unroll
            for (int i = 0; i < 8; i++)
#pragma unroll
                for (int j = 0; j < 4; j++)
                    acc[i][j] = fmaf(ar[i], br[j], acc[i][j]);
        }
        __syncthreads();
    }

#pragma unroll
    for (int i = 0; i < 8; i++) {
        int r = bm + ty * 8 + i;
        if (r < M) {
            float4 o = make_float4(acc[i][0], acc[i][1], acc[i][2], acc[i][3]);
            *(float4*)(C + (size_t)r * N + bn + tx * 4) = o;
        }
    }
}

// ---------------- fused aggregate + bias + nan_to_num + LN + skip + relu ---
// one warp per node; lane owns channels [4*lane,4*lane+4) and [128+4*lane, ...)
__global__ __launch_bounds__(256) void agg_ln_k(
                         const float* __restrict__ hprev,
                         const float* __restrict__ bias,
                         const float* __restrict__ gamma,
                         const float* __restrict__ beta,
                         float* __restrict__ out,
                         int add_skip, int do_relu) {
    int w    = (blockIdx.x * blockDim.x + threadIdx.x) >> 5;
    int lane = threadIdx.x & 31;
    if (w >= NN) return;

    const float* hw = g_hw;
    const float4* base = (const float4*)(hw + (size_t)w * 256);
    float d  = g_dis[w];
    float sc = d * d;
    float4 v0 = base[lane];
    float4 v1 = base[lane + 32];
    float a[8];
    a[0] = sc * v0.x; a[1] = sc * v0.y; a[2] = sc * v0.z; a[3] = sc * v0.w;
    a[4] = sc * v1.x; a[5] = sc * v1.y; a[6] = sc * v1.z; a[7] = sc * v1.w;

    int beg = g_rowptr[w];
    int end = g_rowptr[w + 1];
    int e = beg;

    // unrolled x4: 8 independent float4 loads in flight per iteration
    for (; e + 4 <= end; e += 4) {
        int   s0 = g_srcs[e + 0], s1 = g_srcs[e + 1];
        int   s2 = g_srcs[e + 2], s3 = g_srcs[e + 3];
        float c0 = g_coef[e + 0], c1 = g_coef[e + 1];
        float c2 = g_coef[e + 2], c3 = g_coef[e + 3];
        const float4* p0 = (const float4*)(hw + (size_t)s0 * 256);
        const float4* p1 = (const float4*)(hw + (size_t)s1 * 256);
        const float4* p2 = (const float4*)(hw + (size_t)s2 * 256);
        const float4* p3 = (const float4*)(hw + (size_t)s3 * 256);
        float4 x00 = p0[lane], x01 = p0[lane + 32];
        float4 x10 = p1[lane], x11 = p1[lane + 32];
        float4 x20 = p2[lane], x21 = p2[lane + 32];
        float4 x30 = p3[lane], x31 = p3[lane + 32];

        a[0] = fmaf(c0, x00.x, a[0]); a[1] = fmaf(c0, x00.y, a[1]);
        a[2] = fmaf(c0, x00.z, a[2]); a[3] = fmaf(c0, x00.w, a[3]);
        a[4] = fmaf(c0, x01.x, a[4]); a[5] = fmaf(c0, x01.y, a[5]);
        a[6] = fmaf(c0, x01.z, a[6]); a[7] = fmaf(c0, x01.w, a[7]);

        a[0] = fmaf(c1, x10.x, a[0]); a[1] = fmaf(c1, x10.y, a[1]);
        a[2] = fmaf(c1, x10.z, a[2]); a[3] = fmaf(c1, x10.w, a[3]);
        a[4] = fmaf(c1, x11.x, a[4]); a[5] = fmaf(c1, x11.y, a[5]);
        a[6] = fmaf(c1, x11.z, a[6]); a[7] = fmaf(c1, x11.w, a[7]);

        a[0] = fmaf(c2, x20.x, a[0]); a[1] = fmaf(c2, x20.y, a[1]);
        a[2] = fmaf(c2, x20.z, a[2]); a[3] = fmaf(c2, x20.w, a[3]);
        a[4] = fmaf(c2, x21.x, a[4]); a[5] = fmaf(c2, x21.y, a[5]);
        a[6] = fmaf(c2, x21.z, a[6]); a[7] = fmaf(c2, x21.w, a[7]);

        a[0] = fmaf(c3, x30.x, a[0]); a[1] = fmaf(c3, x30.y, a[1]);
        a[2] = fmaf(c3, x30.z, a[2]); a[3] = fmaf(c3, x30.w, a[3]);
        a[4] = fmaf(c3, x31.x, a[4]); a[5] = fmaf(c3, x31.y, a[5]);
        a[6] = fmaf(c3, x31.z, a[6]); a[7] = fmaf(c3, x31.w, a[7]);
    }
    for (; e < end; e++) {
        int   s = g_srcs[e];
        float c = g_coef[e];
        const float4* p = (const float4*)(hw + (size_t)s * 256);
        float4 x0 = p[lane];
        float4 x1 = p[lane + 32];
        a[0] = fmaf(c, x0.x, a[0]); a[1] = fmaf(c, x0.y, a[1]);
        a[2] = fmaf(c, x0.z, a[2]); a[3] = fmaf(c, x0.w, a[3]);
        a[4] = fmaf(c, x1.x, a[4]); a[5] = fmaf(c, x1.y, a[5]);
        a[6] = fmaf(c, x1.z, a[6]); a[7] = fmaf(c, x1.w, a[7]);
    }

    float4 b0 = ((const float4*)bias)[lane];
    float4 b1 = ((const float4*)bias)[lane + 32];
    a[0] += b0.x; a[1] += b0.y; a[2] += b0.z; a[3] += b0.w;
    a[4] += b1.x; a[5] += b1.y; a[6] += b1.z; a[7] += b1.w;

    // nan_to_num(nan=0, posinf=EPS, neginf=-EPS)
#pragma unroll
    for (int i = 0; i < 8; i++) {
        float f = a[i];
        if (f != f) f = 0.f;
        else if (isinf(f)) f = (f > 0.f) ? EPSV : -EPSV;
        a[i] = f;
    }

    // mean
    float s = 0.f;
#pragma unroll
    for (int i = 0; i < 8; i++) s += a[i];
#pragma unroll
    for (int off = 16; off > 0; off >>= 1) s += __shfl_xor_sync(0xffffffffu, s, off);
    float mean = s * (1.0f / 256.0f);

    // var
    float v = 0.f;
#pragma unroll
    for (int i = 0; i < 8; i++) {
        float xc = a[i] - mean;
        a[i] = xc;
        v = fmaf(xc, xc, v);
    }
#pragma unroll
    for (int off = 16; off > 0; off >>= 1) v += __shfl_xor_sync(0xffffffffu, v, off);
    float inv = rsqrtf(v * (1.0f / 256.0f) + EPSV);

    float4 g0  = ((const float4*)gamma)[lane];
    float4 g1  = ((const float4*)gamma)[lane + 32];
    float4 be0 = ((const float4*)beta)[lane];
    float4 be1 = ((const float4*)beta)[lane + 32];

    float o[8];
    o[0] = a[0] * inv * g0.x + be0.x;
    o[1] = a[1] * inv * g0.y + be0.y;
    o[2] = a[2] * inv * g0.z + be0.z;
    o[3] = a[3] * inv * g0.w + be0.w;
    o[4] = a[4] * inv * g1.x + be1.x;
    o[5] = a[5] * inv * g1.y + be1.y;
    o[6] = a[6] * inv * g1.z + be1.z;
    o[7] = a[7] * inv * g1.w + be1.w;

    if (add_skip) {
        const float4* pp = (const float4*)(hprev + (size_t)w * 256);
        float4 p0 = pp[lane];
        float4 p1 = pp[lane + 32];
        o[0] += p0.x; o[1] += p0.y; o[2] += p0.z; o[3] += p0.w;
        o[4] += p1.x; o[5] += p1.y; o[6] += p1.z; o[7] += p1.w;
    }
    if (do_relu) {
#pragma unroll
        for (int i = 0; i < 8; i++) o[i] = fmaxf(o[i], 0.f);
    }

    float4* ov = (float4*)(out + (size_t)w * 256);
    ov[lane]      = make_float4(o[0], o[1], o[2], o[3]);
    ov[lane + 32] = make_float4(o[4], o[5], o[6], o[7]);
}

// ---------------- launch ---------------------------------------------------
extern "C" void kernel_launch(void* const* d_in, const int* in_sizes, int n_in,
                              void* d_out, int out_size) {
    const float* x  = (const float*)d_in[0];
    const int*   ei = (const int*)d_in[1];
    // per layer i: W = d_in[2+4i], b = d_in[3+4i], g = d_in[4+4i], be = d_in[5+4i]

    float* hbase;
    float* hwp;
    cudaGetSymbolAddress((void**)&hbase, g_h);
    cudaGetSymbolAddress((void**)&hwp, g_hw);
    float* hA = hbase;
    float* hB = hbase + (size_t)NN * 256;

    // CSR build (per call; edge_index is an input)
    zero_counts_k<<<(NN + 255) / 256, 256>>>();
    hist_k<<<(NE + 255) / 256, 256>>>(ei);
    scan_k<<<1, 1024>>>();
    scatter_k<<<(NE + 255) / 256, 256>>>(ei);

    dim3 gemm_grid(256 / 64, (NN + 127) / 128);
    int agg_blocks = (NN + 7) / 8;   // 8 warps (256 threads) per block

    // ---- layer 0: x[*,128] -> hA ----
    gemm_k<<<gemm_grid, 256>>>(x, (const float*)d_in[2], hwp, NN, 128);
    agg_ln_k<<<agg_blocks, 256>>>(nullptr, (const float*)d_in[3],
                                  (const float*)d_in[4], (const float*)d_in[5],
                                  hA, /*skip=*/0, /*relu=*/1);
    // ---- layer 1: hA -> hB ----
    gemm_k<<<gemm_grid, 256>>>(hA, (const float*)d_in[6], hwp, NN, 256);
    agg_ln_k<<<agg_blocks, 256>>>(hA, (const float*)d_in[7],
                                  (const float*)d_in[8], (const float*)d_in[9],
                                  hB, 1, 1);
    // ---- layer 2: hB -> hA ----
    gemm_k<<<gemm_grid, 256>>>(hB, (const float*)d_in[10], hwp, NN, 256);
    agg_ln_k<<<agg_blocks, 256>>>(hB, (const float*)d_in[11],
                                  (const float*)d_in[12], (const float*)d_in[13],
                                  hA, 1, 1);
    // ---- layer 3: hA -> d_out (no relu) ----
    gemm_k<<<gemm_grid, 256>>>(hA, (const float*)d_in[14], hwp, NN, 256);
    agg_ln_k<<<agg_blocks, 256>>>(hA, (const float*)d_in[15],
                                  (const float*)d_in[16], (const float*)d_in[17],
                                  (float*)d_out, 1, 0);
}

// round 7
// speedup vs baseline: 1.0953x; 1.0953x over previous
#include <cuda_runtime.h>
#include <math.h>
#include <stdint.h>

#define NN 50000
#define NE 1600000
#define EPSV 1e-5f

// ---------------- scratch (device globals; no allocation allowed) ----------
__device__ float g_h[2][(size_t)NN * 256];      // ping-pong hidden states
__device__ float g_hw[(size_t)NN * 256];        // h @ W
__device__ int   g_counts[NN];
__device__ int   g_rowptr[NN + 1];
__device__ int   g_fill[NN];
__device__ int2  g_edge[NE];                    // {src, coef-as-bits}
__device__ float g_dis[NN];

// ---------------- CSR build ------------------------------------------------
__global__ void zero_counts_k() {
    int i = blockIdx.x * blockDim.x + threadIdx.x;
    if (i < NN) g_counts[i] = 0;
}

__global__ void hist_k(const int* __restrict__ ei) {
    int e = blockIdx.x * blockDim.x + threadIdx.x;
    if (e < NE) atomicAdd(&g_counts[ei[NE + e]], 1);
}

// single block, 1024 threads: exclusive scan of counts -> rowptr, fill; dis
__global__ void scan_k() {
    __shared__ int sh[1024];
    int t = threadIdx.x;
    const int per = (NN + 1023) / 1024;
    int beg = t * per;
    int end = beg + per; if (end > NN) end = NN;
    if (beg > NN) beg = NN;
    int s = 0;
    for (int i = beg; i < end; i++) s += g_counts[i];
    sh[t] = s;
    __syncthreads();
    if (t == 0) {
        int acc = 0;
        for (int i = 0; i < 1024; i++) { int v = sh[i]; sh[i] = acc; acc += v; }
    }
    __syncthreads();
    int off = sh[t];
    for (int i = beg; i < end; i++) {
        g_rowptr[i] = off;
        g_fill[i]   = off;
        int c = g_counts[i];
        off += c;
        g_dis[i] = rsqrtf((float)c + 1.0f);
    }
    if (end == NN) g_rowptr[NN] = off;  // all tail threads write the same total
}

__global__ void scatter_k(const int* __restrict__ ei) {
    int e = blockIdx.x * blockDim.x + threadIdx.x;
    if (e < NE) {
        int s = ei[e];
        int d = ei[NE + e];
        int pos = atomicAdd(&g_fill[d], 1);
        float c = g_dis[s] * g_dis[d];
        g_edge[pos] = make_int2(s, __float_as_int(c));
    }
}

// ---------------- tensor-core GEMM (3xTF32 split, fp32-accurate) -----------
// C[M,256] = A[M,K] * B[K,256].  BM=64, BN=128, BK=16, 256 threads (8 warps).
// Warp grid 2(m) x 4(n); each warp computes 32x32 via m16n8k8 mma tiles.

__device__ __forceinline__ uint32_t f2tf32(float x) {
    uint32_t r;
    asm("cvt.rna.tf32.f32 %0, %1;" : "=r"(r) : "f"(x));
    return r;
}

__device__ __forceinline__ void mma_tf32(float* d, const uint32_t* a, const uint32_t* b) {
    asm volatile(
        "mma.sync.aligned.m16n8k8.row.col.f32.tf32.tf32.f32 "
        "{%0,%1,%2,%3}, {%4,%5,%6,%7}, {%8,%9}, {%0,%1,%2,%3};"
        : "+f"(d[0]), "+f"(d[1]), "+f"(d[2]), "+f"(d[3])
        : "r"(a[0]), "r"(a[1]), "r"(a[2]), "r"(a[3]),
          "r"(b[0]), "r"(b[1]));
}

#define ASTRIDE 72    // k-major A tile stride: 72 mod 32 = 8 -> conflict-free frags
#define BSTRIDE 136   // k-major B tile stride: 136 mod 32 = 8 -> conflict-free frags
                      // BSTRIDE*4 = 544 bytes, 16B-aligned -> uint4 row stores OK

__global__ __launch_bounds__(256) void gemm_tc_k(
        const float* __restrict__ A, const float* __restrict__ B,
        float* __restrict__ C, int M, int K) {
    const int N = 256;
    __shared__ uint32_t Ah[16][ASTRIDE];   // [k][m], m<64
    __shared__ uint32_t Al[16][ASTRIDE];
    __shared__ uint32_t Bh[16][BSTRIDE];   // [k][n], n<128
    __shared__ uint32_t Bl[16][BSTRIDE];

    int t    = threadIdx.x;
    int warp = t >> 5;
    int lane = t & 31;
    int g    = lane >> 2;      // group id 0..7
    int tg   = lane & 3;       // thread-in-group 0..3

    int bm = blockIdx.y * 64;
    int bn = blockIdx.x * 128;
    int m_warp = (warp & 1) * 32;
    int n_warp = (warp >> 1) * 32;

    // A tile loader mapping: 64x16 floats = 1 float4/thread
    int a_row = t >> 2;          // 0..63
    int a_c4  = (t & 3) * 4;     // 0,4,8,12

    float acc[2][4][4];
#pragma unroll
    for (int mi = 0; mi < 2; mi++)
#pragma unroll
        for (int ni = 0; ni < 4; ni++)
#pragma unroll
            for (int j = 0; j < 4; j++) acc[mi][ni][j] = 0.f;

    for (int k0 = 0; k0 < K; k0 += 16) {
        // ---- stage A (convert to hi/lo tf32; transposed scalar stores) ----
        {
            int r = bm + a_row;
            float4 av = make_float4(0.f, 0.f, 0.f, 0.f);
            if (r < M) av = *(const float4*)(A + (size_t)r * K + k0 + a_c4);
            float vals[4] = {av.x, av.y, av.z, av.w};
#pragma unroll
            for (int j = 0; j < 4; j++) {
                float f = vals[j];
                uint32_t hb = f2tf32(f);
                float lo = f - __uint_as_float(hb);
                Ah[a_c4 + j][a_row] = hb;
                Al[a_c4 + j][a_row] = f2tf32(lo);
            }
        }
        // ---- stage B (vectorized STS.128, conflict-free) ----
#pragma unroll
        for (int rep = 0; rep < 2; rep++) {
            int fi  = t + rep * 256;
            int row = fi >> 5;          // 0..15
            int c4  = (fi & 31) * 4;    // 0..124
            float4 bv = *(const float4*)(B + (size_t)(k0 + row) * N + bn + c4);
            float vals[4] = {bv.x, bv.y, bv.z, bv.w};
            uint32_t hbv[4], lbv[4];
#pragma unroll
            for (int j = 0; j < 4; j++) {
                float f = vals[j];
                hbv[j] = f2tf32(f);
                lbv[j] = f2tf32(f - __uint_as_float(hbv[j]));
            }
            *(uint4*)&Bh[row][c4] = make_uint4(hbv[0], hbv[1], hbv[2], hbv[3]);
            *(uint4*)&Bl[row][c4] = make_uint4(lbv[0], lbv[1], lbv[2], lbv[3]);
        }
        __syncthreads();

#pragma unroll
        for (int kk = 0; kk < 16; kk += 8) {
            uint32_t ah[2][4], al[2][4], bh[4][2], bl[4][2];
#pragma unroll
            for (int mi = 0; mi < 2; mi++) {
                int m = m_warp + mi * 16 + g;
                ah[mi][0] = Ah[kk + tg][m];
                ah[mi][1] = Ah[kk + tg][m + 8];
                ah[mi][2] = Ah[kk + tg + 4][m];
                ah[mi][3] = Ah[kk + tg + 4][m + 8];
                al[mi][0] = Al[kk + tg][m];
                al[mi][1] = Al[kk + tg][m + 8];
                al[mi][2] = Al[kk + tg + 4][m];
                al[mi][3] = Al[kk + tg + 4][m + 8];
            }
#pragma unroll
            for (int ni = 0; ni < 4; ni++) {
                int n = n_warp + ni * 8 + g;
                bh[ni][0] = Bh[kk + tg][n];
                bh[ni][1] = Bh[kk + tg + 4][n];
                bl[ni][0] = Bl[kk + tg][n];
                bl[ni][1] = Bl[kk + tg + 4][n];
            }
#pragma unroll
            for (int mi = 0; mi < 2; mi++)
#pragma unroll
                for (int ni = 0; ni < 4; ni++) {
                    mma_tf32(acc[mi][ni], ah[mi], bh[ni]);   // hi*hi
                    mma_tf32(acc[mi][ni], ah[mi], bl[ni]);   // hi*lo
                    mma_tf32(acc[mi][ni], al[mi], bh[ni]);   // lo*hi
                }
        }
        __syncthreads();
    }

    // ---- epilogue ----
#pragma unroll
    for (int mi = 0; mi < 2; mi++) {
        int r0 = bm + m_warp + mi * 16 + g;
        int r1 = r0 + 8;
#pragma unroll
        for (int ni = 0; ni < 4; ni++) {
            int c = bn + n_warp + ni * 8 + 2 * tg;
            if (r0 < M)
                *(float2*)(C + (size_t)r0 * N + c) =
                    make_float2(acc[mi][ni][0], acc[mi][ni][1]);
            if (r1 < M)
                *(float2*)(C + (size_t)r1 * N + c) =
                    make_float2(acc[mi][ni][2], acc[mi][ni][3]);
        }
    }
}

// ---------------- fused aggregate + bias + nan_to_num + LN + skip + relu ---
// one warp per node; lane owns channels [4*lane,4*lane+4) and [128+4*lane, ...)
__global__ __launch_bounds__(256) void agg_ln_k(
                         const float* __restrict__ hprev,
                         const float* __restrict__ bias,
                         const float* __restrict__ gamma,
                         const float* __restrict__ beta,
                         float* __restrict__ out,
                         int add_skip, int do_relu) {
    int w    = (blockIdx.x * blockDim.x + threadIdx.x) >> 5;
    int lane = threadIdx.x & 31;
    if (w >= NN) return;

    const float* hw = g_hw;
    const float4* base = (const float4*)(hw + (size_t)w * 256);
    float d  = g_dis[w];
    float sc = d * d;
    float4 v0 = base[lane];
    float4 v1 = base[lane + 32];
    float a[8];
    a[0] = sc * v0.x; a[1] = sc * v0.y; a[2] = sc * v0.z; a[3] = sc * v0.w;
    a[4] = sc * v1.x; a[5] = sc * v1.y; a[6] = sc * v1.z; a[7] = sc * v1.w;

    int beg = g_rowptr[w];
    int end = g_rowptr[w + 1];
    int e = beg;

    // unrolled x4: 8 independent float4 payload loads in flight per iteration
    for (; e + 4 <= end; e += 4) {
        int2 e0 = g_edge[e + 0], e1 = g_edge[e + 1];
        int2 e2 = g_edge[e + 2], e3 = g_edge[e + 3];
        float c0 = __int_as_float(e0.y), c1 = __int_as_float(e1.y);
        float c2 = __int_as_float(e2.y), c3 = __int_as_float(e3.y);
        const float4* p0 = (const float4*)(hw + (size_t)e0.x * 256);
        const float4* p1 = (const float4*)(hw + (size_t)e1.x * 256);
        const float4* p2 = (const float4*)(hw + (size_t)e2.x * 256);
        const float4* p3 = (const float4*)(hw + (size_t)e3.x * 256);
        float4 x00 = p0[lane], x01 = p0[lane + 32];
        float4 x10 = p1[lane], x11 = p1[lane + 32];
        float4 x20 = p2[lane], x21 = p2[lane + 32];
        float4 x30 = p3[lane], x31 = p3[lane + 32];

        a[0] = fmaf(c0, x00.x, a[0]); a[1] = fmaf(c0, x00.y, a[1]);
        a[2] = fmaf(c0, x00.z, a[2]); a[3] = fmaf(c0, x00.w, a[3]);
        a[4] = fmaf(c0, x01.x, a[4]); a[5] = fmaf(c0, x01.y, a[5]);
        a[6] = fmaf(c0, x01.z, a[6]); a[7] = fmaf(c0, x01.w, a[7]);

        a[0] = fmaf(c1, x10.x, a[0]); a[1] = fmaf(c1, x10.y, a[1]);
        a[2] = fmaf(c1, x10.z, a[2]); a[3] = fmaf(c1, x10.w, a[3]);
        a[4] = fmaf(c1, x11.x, a[4]); a[5] = fmaf(c1, x11.y, a[5]);
        a[6] = fmaf(c1, x11.z, a[6]); a[7] = fmaf(c1, x11.w, a[7]);

        a[0] = fmaf(c2, x20.x, a[0]); a[1] = fmaf(c2, x20.y, a[1]);
        a[2] = fmaf(c2, x20.z, a[2]); a[3] = fmaf(c2, x20.w, a[3]);
        a[4] = fmaf(c2, x21.x, a[4]); a[5] = fmaf(c2, x21.y, a[5]);
        a[6] = fmaf(c2, x21.z, a[6]); a[7] = fmaf(c2, x21.w, a[7]);

        a[0] = fmaf(c3, x30.x, a[0]); a[1] = fmaf(c3, x30.y, a[1]);
        a[2] = fmaf(c3, x30.z, a[2]); a[3] = fmaf(c3, x30.w, a[3]);
        a[4] = fmaf(c3, x31.x, a[4]); a[5] = fmaf(c3, x31.y, a[5]);
        a[6] = fmaf(c3, x31.z, a[6]); a[7] = fmaf(c3, x31.w, a[7]);
    }
    for (; e < end; e++) {
        int2 ed = g_edge[e];
        float c = __int_as_float(ed.y);
        const float4* p = (const float4*)(hw + (size_t)ed.x * 256);
        float4 x0 = p[lane];
        float4 x1 = p[lane + 32];
        a[0] = fmaf(c, x0.x, a[0]); a[1] = fmaf(c, x0.y, a[1]);
        a[2] = fmaf(c, x0.z, a[2]); a[3] = fmaf(c, x0.w, a[3]);
        a[4] = fmaf(c, x1.x, a[4]); a[5] = fmaf(c, x1.y, a[5]);
        a[6] = fmaf(c, x1.z, a[6]); a[7] = fmaf(c, x1.w, a[7]);
    }

    float4 b0 = ((const float4*)bias)[lane];
    float4 b1 = ((const float4*)bias)[lane + 32];
    a[0] += b0.x; a[1] += b0.y; a[2] += b0.z; a[3] += b0.w;
    a[4] += b1.x; a[5] += b1.y; a[6] += b1.z; a[7] += b1.w;

    // nan_to_num(nan=0, posinf=EPS, neginf=-EPS)
#pragma unroll
    for (int i = 0; i < 8; i++) {
        float f = a[i];
        if (f != f) f = 0.f;
        else if (isinf(f)) f = (f > 0.f) ? EPSV : -EPSV;
        a[i] = f;
    }

    // mean
    float s = 0.f;
#pragma unroll
    for (int i = 0; i < 8; i++) s += a[i];
#pragma unroll
    for (int off = 16; off > 0; off >>= 1) s += __shfl_xor_sync(0xffffffffu, s, off);
    float mean = s * (1.0f / 256.0f);

    // var
    float v = 0.f;
#pragma unroll
    for (int i = 0; i < 8; i++) {
        float xc = a[i] - mean;
        a[i] = xc;
        v = fmaf(xc, xc, v);
    }
#pragma unroll
    for (int off = 16; off > 0; off >>= 1) v += __shfl_xor_sync(0xffffffffu, v, off);
    float inv = rsqrtf(v * (1.0f / 256.0f) + EPSV);

    float4 g0  = ((const float4*)gamma)[lane];
    float4 g1  = ((const float4*)gamma)[lane + 32];
    float4 be0 = ((const float4*)beta)[lane];
    float4 be1 = ((const float4*)beta)[lane + 32];

    float o[8];
    o[0] = a[0] * inv * g0.x + be0.x;
    o[1] = a[1] * inv * g0.y + be0.y;
    o[2] = a[2] * inv * g0.z + be0.z;
    o[3] = a[3] * inv * g0.w + be0.w;
    o[4] = a[4] * inv * g1.x + be1.x;
    o[5] = a[5] * inv * g1.y + be1.y;
    o[6] = a[6] * inv * g1.z + be1.z;
    o[7] = a[7] * inv * g1.w + be1.w;

    if (add_skip) {
        const float4* pp = (const float4*)(hprev + (size_t)w * 256);
        float4 p0 = pp[lane];
        float4 p1 = pp[lane + 32];
        o[0] += p0.x; o[1] += p0.y; o[2] += p0.z; o[3] += p0.w;
        o[4] += p1.x; o[5] += p1.y; o[6] += p1.z; o[7] += p1.w;
    }
    if (do_relu) {
#pragma unroll
        for (int i = 0; i < 8; i++) o[i] = fmaxf(o[i], 0.f);
    }

    float4* ov = (float4*)(out + (size_t)w * 256);
    ov[lane]      = make_float4(o[0], o[1], o[2], o[3]);
    ov[lane + 32] = make_float4(o[4], o[5], o[6], o[7]);
}

// ---------------- launch ---------------------------------------------------
extern "C" void kernel_launch(void* const* d_in, const int* in_sizes, int n_in,
                              void* d_out, int out_size) {
    const float* x  = (const float*)d_in[0];
    const int*   ei = (const int*)d_in[1];
    // per layer i: W = d_in[2+4i], b = d_in[3+4i], g = d_in[4+4i], be = d_in[5+4i]

    float* hbase;
    float* hwp;
    cudaGetSymbolAddress((void**)&hbase, g_h);
    cudaGetSymbolAddress((void**)&hwp, g_hw);
    float* hA = hbase;
    float* hB = hbase + (size_t)NN * 256;

    // CSR build (per call; edge_index is an input)
    zero_counts_k<<<(NN + 255) / 256, 256>>>();
    hist_k<<<(NE + 255) / 256, 256>>>(ei);
    scan_k<<<1, 1024>>>();
    scatter_k<<<(NE + 255) / 256, 256>>>(ei);

    dim3 gemm_grid(256 / 128, (NN + 63) / 64);
    int agg_blocks = (NN + 7) / 8;   // 8 warps (256 threads) per block

    // ---- layer 0: x[*,128] -> hA ----
    gemm_tc_k<<<gemm_grid, 256>>>(x, (const float*)d_in[2], hwp, NN, 128);
    agg_ln_k<<<agg_blocks, 256>>>(nullptr, (const float*)d_in[3],
                                  (const float*)d_in[4], (const float*)d_in[5],
                                  hA, /*skip=*/0, /*relu=*/1);
    // ---- layer 1: hA -> hB ----
    gemm_tc_k<<<gemm_grid, 256>>>(hA, (const float*)d_in[6], hwp, NN, 256);
    agg_ln_k<<<agg_blocks, 256>>>(hA, (const float*)d_in[7],
                                  (const float*)d_in[8], (const float*)d_in[9],
                                  hB, 1, 1);
    // ---- layer 2: hB -> hA ----
    gemm_tc_k<<<gemm_grid, 256>>>(hB, (const float*)d_in[10], hwp, NN, 256);
    agg_ln_k<<<agg_blocks, 256>>>(hB, (const float*)d_in[11],
                                  (const float*)d_in[12], (const float*)d_in[13],
                                  hA, 1, 1);
    // ---- layer 3: hA -> d_out (no relu) ----
    gemm_tc_k<<<gemm_grid, 256>>>(hA, (const float*)d_in[14], hwp, NN, 256);
    agg_ln_k<<<agg_blocks, 256>>>(hA, (const float*)d_in[15],
                                  (const float*)d_in[16], (const float*)d_in[17],
                                  (float*)d_out, 1, 0);
}